// round 15
// baseline (speedup 1.0000x reference)
#include <cuda_runtime.h>
#include <cuda_fp16.h>
#include <cstdint>

#define E 1280
#define KDIM 588
#define KP 608            // padded K = 19 * 32
#define NPATCH 6016
#define MAXSEQ 2048
#define NB 5

// ---------------- scratch (device globals: no allocation allowed) ----------
__device__ __align__(16) __half g_a_hi[NPATCH * KP];
__device__ __align__(16) __half g_a_lo[NPATCH * KP];   // fl16(a - ahi)
__device__ __align__(16) __half g_b_hi[E * KP];
__device__ __align__(16) float g_x[NPATCH * E];        // pre-LN GEMM result

// ---------------- static image / packing metadata --------------------------
__constant__ int c_H[6]      = {448, 448, 336, 224, 560, 336};
__constant__ int c_W[6]      = {448, 672, 336, 448, 560, 448};
__constant__ int c_h[6]      = {32, 32, 24, 16, 40, 24};
__constant__ int c_w[6]      = {32, 48, 24, 32, 40, 32};
__constant__ int c_wc[6]     = {4, 6, 3, 4, 5, 4};       // w/8 (all w divisible by 8)
__constant__ int c_cumblk[7] = {0, 384, 960, 1176, 1368, 1968, 2256}; // 3*h*wc cum
__constant__ int c_off[7]    = {0, 1024, 2560, 3136, 3648, 5248, 6016};
__constant__ int c_bi[6]     = {0, 1, 2, 2, 3, 4};
__constant__ int c_s[6]      = {0, 0, 0, 576, 0, 0};
__constant__ int c_cov[5]    = {1024, 1536, 1088, 1600, 768};
__constant__ int c_iv[5][4] = {
    {0, 1024, 0, 0},
    {0, 1536, 0, 0},
    {0, 576, 576, 1088},
    {0, 1600, 0, 0},
    {0, 768, 0, 0}};

struct Imgs { const float* p[6]; };

// ---------------- PTX helpers ----------------------------------------------
__device__ __forceinline__ uint32_t smem_u32(const void* p) {
    uint32_t a;
    asm("{ .reg .u64 t; cvta.to.shared.u64 t, %1; cvt.u32.u64 %0, t; }"
        : "=r"(a) : "l"(p));
    return a;
}

#define CP16(dst, src) \
    asm volatile("cp.async.cg.shared.global [%0], [%1], 16;" :: "r"(dst), "l"(src))
#define CP_COMMIT() asm volatile("cp.async.commit_group;" ::: "memory")
#define CP_WAIT(n)  asm volatile("cp.async.wait_group %0;" :: "n"(n) : "memory")

#define LDSM4(r, addr)                                                          \
    asm volatile("ldmatrix.sync.aligned.m8n8.x4.shared.b16 {%0,%1,%2,%3}, [%4];" \
        : "=r"((r)[0]), "=r"((r)[1]), "=r"((r)[2]), "=r"((r)[3]) : "r"(addr))

#define MMA(d, a, b)                                                            \
    asm volatile("mma.sync.aligned.m16n8k16.row.col.f32.f16.f16.f32 "           \
        "{%0,%1,%2,%3}, {%4,%5,%6,%7}, {%8,%9}, {%0,%1,%2,%3};"                 \
        : "+f"((d)[0]), "+f"((d)[1]), "+f"((d)[2]), "+f"((d)[3])                \
        : "r"((a)[0]), "r"((a)[1]), "r"((a)[2]), "r"((a)[3]),                   \
          "r"((b)[0]), "r"((b)[1]))

// ---------------- im2col: npx==8 always (all w % 8 == 0) -------------------
// Block = (image, channel, patch-row, 8-patch chunk). Grid 2256 total.
__global__ __launch_bounds__(256) void a_conv_kernel(Imgs imgs, int blk0) {
    __shared__ float sm[14 * 112];
    __shared__ ushort4 s_idx4[49];    // quad q -> smem offsets of f=4q..4q+3
    int blk = blockIdx.x + blk0;
    int im = 0;
#pragma unroll
    for (int i = 1; i < 6; i++) if (blk >= c_cumblk[i]) im = i;
    int local = blk - c_cumblk[im];
    int h = c_h[im], w = c_w[im], W = c_W[im], H = c_H[im], wc = c_wc[im];
    int ch  = local / (h * wc);
    int rem = local - ch * h * wc;
    int py  = rem / wc;
    int qx  = rem - py * wc;
    int px0 = qx * 8;
    int tid = threadIdx.x;

    const float* src = imgs.p[im] + ((size_t)ch * H + py * 14) * W + px0 * 14;
#pragma unroll
    for (int i = 0; i < 7; i++) {           // 14*112 = 1568 = 6.125*256
        int t = tid + i * 256;
        if (i == 6 && t >= 1568) break;
        int r = t / 112, c = t - r * 112;   // constant divisor
        sm[t] = src[(size_t)r * W + c];
    }
    if (tid < 49) {
        int f = tid * 4;
        ushort4 v;
        v.x = (ushort)(((f    ) / 14) * 112 + ((f    ) % 14));
        v.y = (ushort)(((f + 1) / 14) * 112 + ((f + 1) % 14));
        v.z = (ushort)(((f + 2) / 14) * 112 + ((f + 2) % 14));
        v.w = (ushort)(((f + 3) / 14) * 112 + ((f + 3) % 14));
        s_idx4[tid] = v;
    }
    __syncthreads();

    int gpbase = c_off[im] + py * w + px0;
    int chbase = ch * 196;
#pragma unroll
    for (int i = 0; i < 2; i++) {           // 8*49 = 392 quads
        int t = tid + i * 256;
        if (i == 1 && t >= 392) break;
        int px = t / 49;                    // constant divisor
        int q  = t - px * 49;
        int f  = q * 4;
        int sb = px * 14;
        ushort4 ix = s_idx4[q];
        float v0 = sm[ix.x + sb];
        float v1 = sm[ix.y + sb];
        float v2 = sm[ix.z + sb];
        float v3 = sm[ix.w + sb];
        __half2 h01 = __floats2half2_rn(v0, v1);
        __half2 h23 = __floats2half2_rn(v2, v3);
        float2 f01 = __half22float2(h01);
        float2 f23 = __half22float2(h23);
        __half2 l01 = __floats2half2_rn(v0 - f01.x, v1 - f01.y);
        __half2 l23 = __floats2half2_rn(v2 - f23.x, v3 - f23.y);
        size_t dsth = (size_t)(gpbase + px) * KP + chbase + f;
        uint2 uhi = make_uint2(*(uint32_t*)&h01, *(uint32_t*)&h23);
        uint2 ulo = make_uint2(*(uint32_t*)&l01, *(uint32_t*)&l23);
        *(uint2*)&g_a_hi[dsth] = uhi;
        *(uint2*)&g_a_lo[dsth] = ulo;
    }

    // zero the K padding [588,608): 5 uint2 per patch (ch==2 chunk owns it)
    if (ch == 2 && tid < 40) {
        int px = tid / 5;
        int j  = tid - px * 5;
        uint2 z = make_uint2(0u, 0u);
        size_t dsth = (size_t)(gpbase + px) * KP + KDIM + j * 4;
        *(uint2*)&g_a_hi[dsth] = z;
        *(uint2*)&g_a_lo[dsth] = z;
    }
}

// ---------------- conv_w -> fp16 [N=1280][K=608] ---------------------------
__global__ __launch_bounds__(256) void b_conv_kernel(const float* __restrict__ conv_w) {
    int idx = blockIdx.x * 256 + threadIdx.x;
    if (idx >= E * KP) return;
    int n = idx / KP;
    int k = idx - n * KP;
    float v = (k < KDIM) ? conv_w[n * KDIM + k] : 0.f;
    g_b_hi[idx] = __float2half(v);
}

// ---------------- fp16 2-product HMMA GEMM, tile 64x128, occ 4 -------------
// 128 threads = 4 warps (2x2), warp tile 32x64. BK=32, double-buffered.
#define KROW 40
#define A_TILE (64 * KROW * 2)        // 5120
#define B_TILE (128 * KROW * 2)       // 10240
#define STAGE_B (2 * A_TILE + B_TILE) // 20480
#define SMEM_TOTAL (2 * STAGE_B)      // 40960
#define NITER 19

__global__ __launch_bounds__(128, 4) void gemm_mma(int bm0) {
    extern __shared__ __align__(128) char smem[];
    uint32_t sbase = smem_u32(smem);
    int tid  = threadIdx.x;
    int lane = tid & 31;
    int wid  = tid >> 5;
    int wm = wid >> 1, wn = wid & 1;
    int bm = blockIdx.y + bm0, bn = blockIdx.x;

    const __half* gAhi = g_a_hi + (size_t)bm * 64 * KP;
    const __half* gAlo = g_a_lo + (size_t)bm * 64 * KP;
    const __half* gBhi = g_b_hi + (size_t)bn * 128 * KP;

    float acc[2][8][4];
#pragma unroll
    for (int i = 0; i < 2; i++)
#pragma unroll
        for (int j = 0; j < 8; j++)
#pragma unroll
            for (int q = 0; q < 4; q++) acc[i][j][q] = 0.f;

    // stage = 1024 16B chunks, 8 per thread
    auto load_stage = [&](int buf, int k0) {
        uint32_t st = sbase + buf * STAGE_B;
#pragma unroll
        for (int i = 0; i < 8; i++) {
            int c = tid + i * 128;
            const __half* g;
            uint32_t base;
            int row;
            if (c < 256)      { g = gAhi; base = 0;          row = c >> 2; }
            else if (c < 512) { g = gAlo; base = A_TILE;     row = (c - 256) >> 2; }
            else              { g = gBhi; base = 2 * A_TILE; row = (c - 512) >> 2; }
            int cg = c & 3;
            CP16(st + base + row * (KROW * 2) + cg * 16,
                 g + (size_t)row * KP + k0 + cg * 8);
        }
        CP_COMMIT();
    };

    load_stage(0, 0);

    int a_row = wm * 32 + (lane & 15);
    int a_cg  = (lane >> 4);
    int b_row = wn * 64 + (lane & 7) + ((lane >> 4) << 3);
    int b_cg  = (lane >> 3) & 1;

    for (int it = 0; it < NITER; it++) {
        if (it + 1 < NITER) load_stage((it + 1) & 1, (it + 1) * 32);
        if (it + 1 < NITER) { CP_WAIT(1); } else { CP_WAIT(0); }
        __syncthreads();

        uint32_t st  = sbase + (it & 1) * STAGE_B;
        uint32_t aHi = st;
        uint32_t aLo = st + A_TILE;
        uint32_t bHi = st + 2 * A_TILE;

#pragma unroll
        for (int ks = 0; ks < 2; ks++) {
            uint32_t aoff = a_row * (KROW * 2) + (ks * 16 + a_cg * 8) * 2;
            uint32_t boff = b_row * (KROW * 2) + (ks * 16 + b_cg * 8) * 2;

            uint32_t ar[2][4];
            uint32_t bhi[4][4];   // pair pp covers n-tiles 2pp, 2pp+1

#pragma unroll
            for (int pp = 0; pp < 4; pp++)
                LDSM4(bhi[pp], bHi + boff + pp * 16 * (KROW * 2));
#pragma unroll
            for (int mt = 0; mt < 2; mt++)
                LDSM4(ar[mt], aHi + aoff + mt * 16 * (KROW * 2));

#pragma unroll
            for (int mt = 0; mt < 2; mt++)
#pragma unroll
                for (int pp = 0; pp < 4; pp++) {
                    MMA(acc[mt][pp * 2],     ar[mt], (&bhi[pp][0]));
                    MMA(acc[mt][pp * 2 + 1], ar[mt], (&bhi[pp][2]));
                }
#pragma unroll
            for (int mt = 0; mt < 2; mt++)
                LDSM4(ar[mt], aLo + aoff + mt * 16 * (KROW * 2));
#pragma unroll
            for (int mt = 0; mt < 2; mt++)
#pragma unroll
                for (int pp = 0; pp < 4; pp++) {
                    MMA(acc[mt][pp * 2],     ar[mt], (&bhi[pp][0]));
                    MMA(acc[mt][pp * 2 + 1], ar[mt], (&bhi[pp][2]));
                }
        }
        __syncthreads();
    }

    int g = lane >> 2, t = lane & 3;
    int row0 = bm * 64 + wm * 32;
    int col0 = bn * 128 + wn * 64;
#pragma unroll
    for (int mt = 0; mt < 2; mt++) {
#pragma unroll
        for (int nt = 0; nt < 8; nt++) {
            float* p = g_x + (size_t)(row0 + mt * 16 + g) * E + col0 + nt * 8 + t * 2;
            *(float2*)p           = make_float2(acc[mt][nt][0], acc[mt][nt][1]);
            *(float2*)(p + 8 * E) = make_float2(acc[mt][nt][2], acc[mt][nt][3]);
        }
    }
}

// ---------------- pos-embed interp + bias + LayerNorm + scatter ------------
__global__ __launch_bounds__(256) void ln_kernel(const float* __restrict__ conv_b,
                                                 const float* __restrict__ pos_table,
                                                 const float* __restrict__ ln_w,
                                                 const float* __restrict__ ln_b,
                                                 float* __restrict__ out, int goff) {
    int gp = blockIdx.x + goff;
    int im = 0;
#pragma unroll
    for (int i = 1; i < 6; i++) if (gp >= c_off[i]) im = i;
    int p = gp - c_off[im];
    int h = c_h[im], w = c_w[im];
    int py = p / w, px = p - py * w;

    float cy = (py + 0.5f) * (32.0f / (float)h) - 0.5f;
    cy = fminf(fmaxf(cy, 0.f), 31.f);
    float cx = (px + 0.5f) * (32.0f / (float)w) - 0.5f;
    cx = fminf(fmaxf(cx, 0.f), 31.f);
    int y0 = (int)cy; int y1 = min(y0 + 1, 31); float fy = cy - (float)y0;
    int x0 = (int)cx; int x1 = min(x0 + 1, 31); float fx = cx - (float)x0;

    const float* T00 = pos_table + (size_t)(1 + y0 * 32 + x0) * E;
    const float* T01 = pos_table + (size_t)(1 + y0 * 32 + x1) * E;
    const float* T10 = pos_table + (size_t)(1 + y1 * 32 + x0) * E;
    const float* T11 = pos_table + (size_t)(1 + y1 * 32 + x1) * E;
    float w00 = (1.f - fy) * (1.f - fx), w01 = (1.f - fy) * fx;
    float w10 = fy * (1.f - fx), w11 = fy * fx;

    int tid = threadIdx.x;
    float y[5];
    float s = 0.f, ss = 0.f;
#pragma unroll
    for (int i = 0; i < 5; i++) {
        int f = tid + i * 256;
        float v = g_x[(size_t)gp * E + f] + conv_b[f]
                + w00 * T00[f] + w01 * T01[f] + w10 * T10[f] + w11 * T11[f];
        y[i] = v;
        s += v;
        ss += v * v;
    }

    __shared__ float rs[8], rss[8];
#pragma unroll
    for (int o = 16; o > 0; o >>= 1) {
        s  += __shfl_xor_sync(0xffffffffu, s, o);
        ss += __shfl_xor_sync(0xffffffffu, ss, o);
    }
    if ((tid & 31) == 0) { rs[tid >> 5] = s; rss[tid >> 5] = ss; }
    __syncthreads();
    __shared__ float fm, finv;
    if (tid == 0) {
        float S = 0.f, SS = 0.f;
#pragma unroll
        for (int i = 0; i < 8; i++) { S += rs[i]; SS += rss[i]; }
        float m = S / (float)E;
        fm = m;
        finv = rsqrtf(SS / (float)E - m * m + 1e-5f);
    }
    __syncthreads();
    float m = fm, inv = finv;

    int row = c_bi[im] * MAXSEQ + c_s[im] + p;
    float* o = out + (size_t)row * E;
#pragma unroll
    for (int i = 0; i < 5; i++) {
        int f = tid + i * 256;
        o[f] = (y[i] - m) * inv * ln_w[f] + ln_b[f];
    }
}

// ---------------- merged fill: mask (blocks 0..2559) + zero (2560..5119) ---
__global__ __launch_bounds__(256) void fill_kernel(float4* __restrict__ out,
                                                   float4* __restrict__ mask) {
    int blk = blockIdx.x;
    int tid = threadIdx.x;
    if (blk < 2560) {
        int b  = blk >> 9;
        int r0 = (blk & 511) * 4;
        const int* iv = c_iv[b];
        int lo = -1, hi = -1;
        if (r0 >= iv[0] && r0 < iv[1]) { lo = iv[0]; hi = iv[1]; }
        else if (iv[3] > iv[2] && r0 >= iv[2] && r0 < iv[3]) { lo = iv[2]; hi = iv[3]; }
        float4* base = mask + ((size_t)(b * MAXSEQ + r0) * MAXSEQ) / 4;
#pragma unroll
        for (int i = 0; i < 8; i++) {
            int fidx = tid + i * 256;
            int col  = (fidx & 511) * 4;
            float v = (col >= lo && col < hi) ? 1.f : 0.f;
            base[fidx] = make_float4(v, v, v, v);
        }
    } else {
        int zb = blk - 2560;
        int b  = zb >> 9;
        int r0 = (zb & 511) * 4;
        if (r0 + 4 <= c_cov[b]) return;
        float4* base = out + ((size_t)(b * MAXSEQ + r0) * E) / 4;
        float4 z = make_float4(0.f, 0.f, 0.f, 0.f);
#pragma unroll
        for (int i = 0; i < 5; i++) base[tid + i * 256] = z;
    }
}

// ---------------- launch (exact R14 schedule) -------------------------------
extern "C" void kernel_launch(void* const* d_in, const int* in_sizes, int n_in,
                              void* d_out, int out_size) {
    Imgs imgs;
    for (int i = 0; i < 6; i++) imgs.p[i] = (const float*)d_in[i];
    const float* conv_w = (const float*)d_in[6];
    const float* conv_b = (const float*)d_in[7];
    const float* pos    = (const float*)d_in[8];
    const float* ln_w   = (const float*)d_in[9];
    const float* ln_b   = (const float*)d_in[10];

    float* out  = (float*)d_out;
    float* mask = out + (size_t)NB * MAXSEQ * E;

    static cudaStream_t s2 = nullptr;
    static cudaEvent_t ev_fork = nullptr, ev_b = nullptr, ev_aB = nullptr,
                       ev_g1 = nullptr, ev_ln1 = nullptr;
    if (!s2) {
        cudaStreamCreateWithFlags(&s2, cudaStreamNonBlocking);
        cudaEventCreateWithFlags(&ev_fork, cudaEventDisableTiming);
        cudaEventCreateWithFlags(&ev_b, cudaEventDisableTiming);
        cudaEventCreateWithFlags(&ev_aB, cudaEventDisableTiming);
        cudaEventCreateWithFlags(&ev_g1, cudaEventDisableTiming);
        cudaEventCreateWithFlags(&ev_ln1, cudaEventDisableTiming);
        cudaFuncSetAttribute(gemm_mma, cudaFuncAttributeMaxDynamicSharedMemorySize,
                             SMEM_TOTAL);
    }

    // fork to s2: b_conv, a_conv part B (images 3-5), fills
    cudaEventRecord(ev_fork, 0);
    cudaStreamWaitEvent(s2, ev_fork, 0);
    b_conv_kernel<<<(E * KP + 255) / 256, 256, 0, s2>>>(conv_w);
    cudaEventRecord(ev_b, s2);
    a_conv_kernel<<<2256 - 1176, 256, 0, s2>>>(imgs, 1176);  // images 3-5
    cudaEventRecord(ev_aB, s2);
    fill_kernel<<<5120, 256, 0, s2>>>((float4*)out, (float4*)mask);

    // main stream: a_conv part A (images 0-2), gemm1 (bm 0..56, rows 0..3647)
    a_conv_kernel<<<1176, 256>>>(imgs, 0);
    cudaStreamWaitEvent(0, ev_b, 0);
    gemm_mma<<<dim3(E / 128, 57), 128, SMEM_TOTAL>>>(0);
    cudaEventRecord(ev_g1, 0);

    // s2: LN for rows 0..3647 overlaps gemm2
    cudaStreamWaitEvent(s2, ev_g1, 0);
    ln_kernel<<<3648, 256, 0, s2>>>(conv_b, pos, ln_w, ln_b, out, 0);
    cudaEventRecord(ev_ln1, s2);

    // main: gemm2 (bm 57..93, rows 3648..6015), then its LN
    cudaStreamWaitEvent(0, ev_aB, 0);
    gemm_mma<<<dim3(E / 128, 37), 128, SMEM_TOTAL>>>(57);
    ln_kernel<<<NPATCH - 3648, 256>>>(conv_b, pos, ln_w, ln_b, out, 3648);

    // join
    cudaStreamWaitEvent(0, ev_ln1, 0);
}

// round 16
// speedup vs baseline: 1.0276x; 1.0276x over previous
#include <cuda_runtime.h>
#include <cuda_fp16.h>
#include <cstdint>

#define E 1280
#define KDIM 588
#define KP 608            // padded K = 19 * 32
#define NPATCH 6016
#define MAXSEQ 2048
#define NB 5

// ---------------- scratch (device globals: no allocation allowed) ----------
__device__ __align__(16) __half g_a_hi[NPATCH * KP];
__device__ __align__(16) __half g_a_lo[NPATCH * KP];   // fl16(a - ahi)
__device__ __align__(16) __half g_b_hi[E * KP];
__device__ __align__(16) float g_x[NPATCH * E];        // pre-LN GEMM result

// ---------------- static image / packing metadata --------------------------
__constant__ int c_H[6]      = {448, 448, 336, 224, 560, 336};
__constant__ int c_W[6]      = {448, 672, 336, 448, 560, 448};
__constant__ int c_h[6]      = {32, 32, 24, 16, 40, 24};
__constant__ int c_w[6]      = {32, 48, 24, 32, 40, 32};
__constant__ int c_wc[6]     = {4, 6, 3, 4, 5, 4};       // w/8 (all w divisible by 8)
__constant__ int c_cumblk[7] = {0, 384, 960, 1176, 1368, 1968, 2256}; // 3*h*wc cum
__constant__ int c_off[7]    = {0, 1024, 2560, 3136, 3648, 5248, 6016};
__constant__ int c_bi[6]     = {0, 1, 2, 2, 3, 4};
__constant__ int c_s[6]      = {0, 0, 0, 576, 0, 0};
__constant__ int c_cov[5]    = {1024, 1536, 1088, 1600, 768};
__constant__ int c_iv[5][4] = {
    {0, 1024, 0, 0},
    {0, 1536, 0, 0},
    {0, 576, 576, 1088},
    {0, 1600, 0, 0},
    {0, 768, 0, 0}};

struct Imgs { const float* p[6]; };

// ---------------- PTX helpers ----------------------------------------------
__device__ __forceinline__ uint32_t smem_u32(const void* p) {
    uint32_t a;
    asm("{ .reg .u64 t; cvta.to.shared.u64 t, %1; cvt.u32.u64 %0, t; }"
        : "=r"(a) : "l"(p));
    return a;
}

#define CP16(dst, src) \
    asm volatile("cp.async.cg.shared.global [%0], [%1], 16;" :: "r"(dst), "l"(src))
#define CP_COMMIT() asm volatile("cp.async.commit_group;" ::: "memory")
#define CP_WAIT(n)  asm volatile("cp.async.wait_group %0;" :: "n"(n) : "memory")

#define LDSM4(r, addr)                                                          \
    asm volatile("ldmatrix.sync.aligned.m8n8.x4.shared.b16 {%0,%1,%2,%3}, [%4];" \
        : "=r"((r)[0]), "=r"((r)[1]), "=r"((r)[2]), "=r"((r)[3]) : "r"(addr))

#define MMA(d, a, b)                                                            \
    asm volatile("mma.sync.aligned.m16n8k16.row.col.f32.f16.f16.f32 "           \
        "{%0,%1,%2,%3}, {%4,%5,%6,%7}, {%8,%9}, {%0,%1,%2,%3};"                 \
        : "+f"((d)[0]), "+f"((d)[1]), "+f"((d)[2]), "+f"((d)[3])                \
        : "r"((a)[0]), "r"((a)[1]), "r"((a)[2]), "r"((a)[3]),                   \
          "r"((b)[0]), "r"((b)[1]))

// ---------------- im2col: npx==8 always (all w % 8 == 0) -------------------
__global__ __launch_bounds__(256) void a_conv_kernel(Imgs imgs, int blk0) {
    __shared__ float sm[14 * 112];
    __shared__ ushort4 s_idx4[49];    // quad q -> smem offsets of f=4q..4q+3
    int blk = blockIdx.x + blk0;
    int im = 0;
#pragma unroll
    for (int i = 1; i < 6; i++) if (blk >= c_cumblk[i]) im = i;
    int local = blk - c_cumblk[im];
    int h = c_h[im], w = c_w[im], W = c_W[im], H = c_H[im], wc = c_wc[im];
    int ch  = local / (h * wc);
    int rem = local - ch * h * wc;
    int py  = rem / wc;
    int qx  = rem - py * wc;
    int px0 = qx * 8;
    int tid = threadIdx.x;

    const float* src = imgs.p[im] + ((size_t)ch * H + py * 14) * W + px0 * 14;
#pragma unroll
    for (int i = 0; i < 7; i++) {           // 14*112 = 1568
        int t = tid + i * 256;
        if (i == 6 && t >= 1568) break;
        int r = t / 112, c = t - r * 112;
        sm[t] = src[(size_t)r * W + c];
    }
    if (tid < 49) {
        int f = tid * 4;
        ushort4 v;
        v.x = (ushort)(((f    ) / 14) * 112 + ((f    ) % 14));
        v.y = (ushort)(((f + 1) / 14) * 112 + ((f + 1) % 14));
        v.z = (ushort)(((f + 2) / 14) * 112 + ((f + 2) % 14));
        v.w = (ushort)(((f + 3) / 14) * 112 + ((f + 3) % 14));
        s_idx4[tid] = v;
    }
    __syncthreads();

    int gpbase = c_off[im] + py * w + px0;
    int chbase = ch * 196;
#pragma unroll
    for (int i = 0; i < 2; i++) {           // 8*49 = 392 quads
        int t = tid + i * 256;
        if (i == 1 && t >= 392) break;
        int px = t / 49;
        int q  = t - px * 49;
        int f  = q * 4;
        int sb = px * 14;
        ushort4 ix = s_idx4[q];
        float v0 = sm[ix.x + sb];
        float v1 = sm[ix.y + sb];
        float v2 = sm[ix.z + sb];
        float v3 = sm[ix.w + sb];
        __half2 h01 = __floats2half2_rn(v0, v1);
        __half2 h23 = __floats2half2_rn(v2, v3);
        float2 f01 = __half22float2(h01);
        float2 f23 = __half22float2(h23);
        __half2 l01 = __floats2half2_rn(v0 - f01.x, v1 - f01.y);
        __half2 l23 = __floats2half2_rn(v2 - f23.x, v3 - f23.y);
        size_t dsth = (size_t)(gpbase + px) * KP + chbase + f;
        uint2 uhi = make_uint2(*(uint32_t*)&h01, *(uint32_t*)&h23);
        uint2 ulo = make_uint2(*(uint32_t*)&l01, *(uint32_t*)&l23);
        *(uint2*)&g_a_hi[dsth] = uhi;
        *(uint2*)&g_a_lo[dsth] = ulo;
    }

    if (ch == 2 && tid < 40) {
        int px = tid / 5;
        int j  = tid - px * 5;
        uint2 z = make_uint2(0u, 0u);
        size_t dsth = (size_t)(gpbase + px) * KP + KDIM + j * 4;
        *(uint2*)&g_a_hi[dsth] = z;
        *(uint2*)&g_a_lo[dsth] = z;
    }
}

// ---------------- conv_w -> fp16 [N=1280][K=608] ---------------------------
__global__ __launch_bounds__(256) void b_conv_kernel(const float* __restrict__ conv_w) {
    int idx = blockIdx.x * 256 + threadIdx.x;
    if (idx >= E * KP) return;
    int n = idx / KP;
    int k = idx - n * KP;
    float v = (k < KDIM) ? conv_w[n * KDIM + k] : 0.f;
    g_b_hi[idx] = __float2half(v);
}

// ---------------- fp16 2-product HMMA GEMM, tile 64x128, occ 4 -------------
#define KROW 40
#define A_TILE (64 * KROW * 2)        // 5120
#define B_TILE (128 * KROW * 2)       // 10240
#define STAGE_B (2 * A_TILE + B_TILE) // 20480
#define SMEM_TOTAL (2 * STAGE_B)      // 40960
#define NITER 19

__global__ __launch_bounds__(128, 4) void gemm_mma(int bm0) {
    extern __shared__ __align__(128) char smem[];
    uint32_t sbase = smem_u32(smem);
    int tid  = threadIdx.x;
    int lane = tid & 31;
    int wid  = tid >> 5;
    int wm = wid >> 1, wn = wid & 1;
    int bm = blockIdx.y + bm0, bn = blockIdx.x;

    const __half* gAhi = g_a_hi + (size_t)bm * 64 * KP;
    const __half* gAlo = g_a_lo + (size_t)bm * 64 * KP;
    const __half* gBhi = g_b_hi + (size_t)bn * 128 * KP;

    float acc[2][8][4];
#pragma unroll
    for (int i = 0; i < 2; i++)
#pragma unroll
        for (int j = 0; j < 8; j++)
#pragma unroll
            for (int q = 0; q < 4; q++) acc[i][j][q] = 0.f;

    auto load_stage = [&](int buf, int k0) {
        uint32_t st = sbase + buf * STAGE_B;
#pragma unroll
        for (int i = 0; i < 8; i++) {
            int c = tid + i * 128;
            const __half* g;
            uint32_t base;
            int row;
            if (c < 256)      { g = gAhi; base = 0;          row = c >> 2; }
            else if (c < 512) { g = gAlo; base = A_TILE;     row = (c - 256) >> 2; }
            else              { g = gBhi; base = 2 * A_TILE; row = (c - 512) >> 2; }
            int cg = c & 3;
            CP16(st + base + row * (KROW * 2) + cg * 16,
                 g + (size_t)row * KP + k0 + cg * 8);
        }
        CP_COMMIT();
    };

    load_stage(0, 0);

    int a_row = wm * 32 + (lane & 15);
    int a_cg  = (lane >> 4);
    int b_row = wn * 64 + (lane & 7) + ((lane >> 4) << 3);
    int b_cg  = (lane >> 3) & 1;

    for (int it = 0; it < NITER; it++) {
        if (it + 1 < NITER) load_stage((it + 1) & 1, (it + 1) * 32);
        if (it + 1 < NITER) { CP_WAIT(1); } else { CP_WAIT(0); }
        __syncthreads();

        uint32_t st  = sbase + (it & 1) * STAGE_B;
        uint32_t aHi = st;
        uint32_t aLo = st + A_TILE;
        uint32_t bHi = st + 2 * A_TILE;

#pragma unroll
        for (int ks = 0; ks < 2; ks++) {
            uint32_t aoff = a_row * (KROW * 2) + (ks * 16 + a_cg * 8) * 2;
            uint32_t boff = b_row * (KROW * 2) + (ks * 16 + b_cg * 8) * 2;

            uint32_t ar[2][4];
            uint32_t bhi[4][4];

#pragma unroll
            for (int pp = 0; pp < 4; pp++)
                LDSM4(bhi[pp], bHi + boff + pp * 16 * (KROW * 2));
#pragma unroll
            for (int mt = 0; mt < 2; mt++)
                LDSM4(ar[mt], aHi + aoff + mt * 16 * (KROW * 2));

#pragma unroll
            for (int mt = 0; mt < 2; mt++)
#pragma unroll
                for (int pp = 0; pp < 4; pp++) {
                    MMA(acc[mt][pp * 2],     ar[mt], (&bhi[pp][0]));
                    MMA(acc[mt][pp * 2 + 1], ar[mt], (&bhi[pp][2]));
                }
#pragma unroll
            for (int mt = 0; mt < 2; mt++)
                LDSM4(ar[mt], aLo + aoff + mt * 16 * (KROW * 2));
#pragma unroll
            for (int mt = 0; mt < 2; mt++)
#pragma unroll
                for (int pp = 0; pp < 4; pp++) {
                    MMA(acc[mt][pp * 2],     ar[mt], (&bhi[pp][0]));
                    MMA(acc[mt][pp * 2 + 1], ar[mt], (&bhi[pp][2]));
                }
        }
        __syncthreads();
    }

    int g = lane >> 2, t = lane & 3;
    int row0 = bm * 64 + wm * 32;
    int col0 = bn * 128 + wn * 64;
#pragma unroll
    for (int mt = 0; mt < 2; mt++) {
#pragma unroll
        for (int nt = 0; nt < 8; nt++) {
            float* p = g_x + (size_t)(row0 + mt * 16 + g) * E + col0 + nt * 8 + t * 2;
            *(float2*)p           = make_float2(acc[mt][nt][0], acc[mt][nt][1]);
            *(float2*)(p + 8 * E) = make_float2(acc[mt][nt][2], acc[mt][nt][3]);
        }
    }
}

// ---------------- pos-embed interp + bias + LayerNorm + scatter ------------
__global__ __launch_bounds__(256) void ln_kernel(const float* __restrict__ conv_b,
                                                 const float* __restrict__ pos_table,
                                                 const float* __restrict__ ln_w,
                                                 const float* __restrict__ ln_b,
                                                 float* __restrict__ out, int goff) {
    int gp = blockIdx.x + goff;
    int im = 0;
#pragma unroll
    for (int i = 1; i < 6; i++) if (gp >= c_off[i]) im = i;
    int p = gp - c_off[im];
    int h = c_h[im], w = c_w[im];
    int py = p / w, px = p - py * w;

    float cy = (py + 0.5f) * (32.0f / (float)h) - 0.5f;
    cy = fminf(fmaxf(cy, 0.f), 31.f);
    float cx = (px + 0.5f) * (32.0f / (float)w) - 0.5f;
    cx = fminf(fmaxf(cx, 0.f), 31.f);
    int y0 = (int)cy; int y1 = min(y0 + 1, 31); float fy = cy - (float)y0;
    int x0 = (int)cx; int x1 = min(x0 + 1, 31); float fx = cx - (float)x0;

    const float* T00 = pos_table + (size_t)(1 + y0 * 32 + x0) * E;
    const float* T01 = pos_table + (size_t)(1 + y0 * 32 + x1) * E;
    const float* T10 = pos_table + (size_t)(1 + y1 * 32 + x0) * E;
    const float* T11 = pos_table + (size_t)(1 + y1 * 32 + x1) * E;
    float w00 = (1.f - fy) * (1.f - fx), w01 = (1.f - fy) * fx;
    float w10 = fy * (1.f - fx), w11 = fy * fx;

    int tid = threadIdx.x;
    float y[5];
    float s = 0.f, ss = 0.f;
#pragma unroll
    for (int i = 0; i < 5; i++) {
        int f = tid + i * 256;
        float v = g_x[(size_t)gp * E + f] + conv_b[f]
                + w00 * T00[f] + w01 * T01[f] + w10 * T10[f] + w11 * T11[f];
        y[i] = v;
        s += v;
        ss += v * v;
    }

    __shared__ float rs[8], rss[8];
#pragma unroll
    for (int o = 16; o > 0; o >>= 1) {
        s  += __shfl_xor_sync(0xffffffffu, s, o);
        ss += __shfl_xor_sync(0xffffffffu, ss, o);
    }
    if ((tid & 31) == 0) { rs[tid >> 5] = s; rss[tid >> 5] = ss; }
    __syncthreads();
    __shared__ float fm, finv;
    if (tid == 0) {
        float S = 0.f, SS = 0.f;
#pragma unroll
        for (int i = 0; i < 8; i++) { S += rs[i]; SS += rss[i]; }
        float m = S / (float)E;
        fm = m;
        finv = rsqrtf(SS / (float)E - m * m + 1e-5f);
    }
    __syncthreads();
    float m = fm, inv = finv;

    int row = c_bi[im] * MAXSEQ + c_s[im] + p;
    float* o = out + (size_t)row * E;
#pragma unroll
    for (int i = 0; i < 5; i++) {
        int f = tid + i * 256;
        o[f] = (y[i] - m) * inv * ln_w[f] + ln_b[f];
    }
}

// ---------------- merged fill: mask (blocks 0..2559) + zero (2560..5119) ---
__global__ __launch_bounds__(256) void fill_kernel(float4* __restrict__ out,
                                                   float4* __restrict__ mask) {
    int blk = blockIdx.x;
    int tid = threadIdx.x;
    if (blk < 2560) {
        int b  = blk >> 9;
        int r0 = (blk & 511) * 4;
        const int* iv = c_iv[b];
        int lo = -1, hi = -1;
        if (r0 >= iv[0] && r0 < iv[1]) { lo = iv[0]; hi = iv[1]; }
        else if (iv[3] > iv[2] && r0 >= iv[2] && r0 < iv[3]) { lo = iv[2]; hi = iv[3]; }
        float4* base = mask + ((size_t)(b * MAXSEQ + r0) * MAXSEQ) / 4;
#pragma unroll
        for (int i = 0; i < 8; i++) {
            int fidx = tid + i * 256;
            int col  = (fidx & 511) * 4;
            float v = (col >= lo && col < hi) ? 1.f : 0.f;
            base[fidx] = make_float4(v, v, v, v);
        }
    } else {
        int zb = blk - 2560;
        int b  = zb >> 9;
        int r0 = (zb & 511) * 4;
        if (r0 + 4 <= c_cov[b]) return;
        float4* base = out + ((size_t)(b * MAXSEQ + r0) * E) / 4;
        float4 z = make_float4(0.f, 0.f, 0.f, 0.f);
#pragma unroll
        for (int i = 0; i < 5; i++) base[tid + i * 256] = z;
    }
}

// ---------------- launch: 3-stream pipelined schedule -----------------------
extern "C" void kernel_launch(void* const* d_in, const int* in_sizes, int n_in,
                              void* d_out, int out_size) {
    Imgs imgs;
    for (int i = 0; i < 6; i++) imgs.p[i] = (const float*)d_in[i];
    const float* conv_w = (const float*)d_in[6];
    const float* conv_b = (const float*)d_in[7];
    const float* pos    = (const float*)d_in[8];
    const float* ln_w   = (const float*)d_in[9];
    const float* ln_b   = (const float*)d_in[10];

    float* out  = (float*)d_out;
    float* mask = out + (size_t)NB * MAXSEQ * E;

    static cudaStream_t s2 = nullptr, s3 = nullptr;
    static cudaEvent_t ev_fork = nullptr, ev_b = nullptr, ev_aB = nullptr,
                       ev_fill = nullptr, ev_g1a = nullptr, ev_g1b = nullptr,
                       ev_ln1 = nullptr;
    if (!s2) {
        cudaStreamCreateWithFlags(&s2, cudaStreamNonBlocking);
        cudaStreamCreateWithFlags(&s3, cudaStreamNonBlocking);
        cudaEventCreateWithFlags(&ev_fork, cudaEventDisableTiming);
        cudaEventCreateWithFlags(&ev_b, cudaEventDisableTiming);
        cudaEventCreateWithFlags(&ev_aB, cudaEventDisableTiming);
        cudaEventCreateWithFlags(&ev_fill, cudaEventDisableTiming);
        cudaEventCreateWithFlags(&ev_g1a, cudaEventDisableTiming);
        cudaEventCreateWithFlags(&ev_g1b, cudaEventDisableTiming);
        cudaEventCreateWithFlags(&ev_ln1, cudaEventDisableTiming);
        cudaFuncSetAttribute(gemm_mma, cudaFuncAttributeMaxDynamicSharedMemorySize,
                             SMEM_TOTAL);
    }

    // fork
    cudaEventRecord(ev_fork, 0);
    cudaStreamWaitEvent(s2, ev_fork, 0);
    cudaStreamWaitEvent(s3, ev_fork, 0);

    // s2: b_conv -> a_convB (images 3-5) -> fill; later ln1
    b_conv_kernel<<<(E * KP + 255) / 256, 256, 0, s2>>>(conv_w);
    cudaEventRecord(ev_b, s2);
    a_conv_kernel<<<2256 - 1176, 256, 0, s2>>>(imgs, 1176);
    cudaEventRecord(ev_aB, s2);
    fill_kernel<<<5120, 256, 0, s2>>>((float4*)out, (float4*)mask);
    cudaEventRecord(ev_fill, s2);

    // s3: a_conv images 1-2 (blocks 384..1175) -> gemm1b (bm 16..48)
    a_conv_kernel<<<1176 - 384, 256, 0, s3>>>(imgs, 384);
    cudaStreamWaitEvent(s3, ev_b, 0);
    gemm_mma<<<dim3(E / 128, 33), 128, SMEM_TOTAL, s3>>>(16);
    cudaEventRecord(ev_g1b, s3);

    // s0: a_conv image 0 (blocks 0..383) -> gemm1a (bm 0..15)
    a_conv_kernel<<<384, 256>>>(imgs, 0);
    cudaStreamWaitEvent(0, ev_b, 0);
    gemm_mma<<<dim3(E / 128, 16), 128, SMEM_TOTAL>>>(0);
    cudaEventRecord(ev_g1a, 0);

    // s2: ln1 (rows 0..3135) after gemm1a + gemm1b, overlaps gemm2
    cudaStreamWaitEvent(s2, ev_g1a, 0);
    cudaStreamWaitEvent(s2, ev_g1b, 0);
    ln_kernel<<<3136, 256, 0, s2>>>(conv_b, pos, ln_w, ln_b, out, 0);
    cudaEventRecord(ev_ln1, s2);

    // s0: gemm2 (bm 49..93, rows 3136..6015 — needs a_convB) -> ln2
    cudaStreamWaitEvent(0, ev_aB, 0);
    gemm_mma<<<dim3(E / 128, 45), 128, SMEM_TOTAL>>>(49);
    ln_kernel<<<NPATCH - 3136, 256>>>(conv_b, pos, ln_w, ln_b, out, 3136);

    // join
    cudaStreamWaitEvent(0, ev_ln1, 0);
    cudaStreamWaitEvent(0, ev_fill, 0);
}

// round 17
// speedup vs baseline: 1.2766x; 1.2424x over previous
#include <cuda_runtime.h>
#include <cuda_fp16.h>
#include <cstdint>

#define E 1280
#define KDIM 588
#define KP 608            // padded K = 19 * 32
#define NPATCH 6016
#define MAXSEQ 2048
#define NB 5

// ---------------- scratch (device globals: no allocation allowed) ----------
__device__ __align__(16) __half g_a_hi[NPATCH * KP];
__device__ __align__(16) __half g_b_hi[E * KP];
__device__ __align__(16) float g_x[NPATCH * E];        // pre-LN GEMM result

// ---------------- static image / packing metadata --------------------------
__constant__ int c_H[6]      = {448, 448, 336, 224, 560, 336};
__constant__ int c_W[6]      = {448, 672, 336, 448, 560, 448};
__constant__ int c_h[6]      = {32, 32, 24, 16, 40, 24};
__constant__ int c_w[6]      = {32, 48, 24, 32, 40, 32};
__constant__ int c_wc[6]     = {4, 6, 3, 4, 5, 4};       // w/8 (all w divisible by 8)
__constant__ int c_cumblk[7] = {0, 384, 960, 1176, 1368, 1968, 2256}; // 3*h*wc cum
__constant__ int c_off[7]    = {0, 1024, 2560, 3136, 3648, 5248, 6016};
__constant__ int c_bi[6]     = {0, 1, 2, 2, 3, 4};
__constant__ int c_s[6]      = {0, 0, 0, 576, 0, 0};
__constant__ int c_cov[5]    = {1024, 1536, 1088, 1600, 768};
__constant__ int c_iv[5][4] = {
    {0, 1024, 0, 0},
    {0, 1536, 0, 0},
    {0, 576, 576, 1088},
    {0, 1600, 0, 0},
    {0, 768, 0, 0}};

struct Imgs { const float* p[6]; };

// ---------------- PTX helpers ----------------------------------------------
__device__ __forceinline__ uint32_t smem_u32(const void* p) {
    uint32_t a;
    asm("{ .reg .u64 t; cvta.to.shared.u64 t, %1; cvt.u32.u64 %0, t; }"
        : "=r"(a) : "l"(p));
    return a;
}

#define CP16(dst, src) \
    asm volatile("cp.async.cg.shared.global [%0], [%1], 16;" :: "r"(dst), "l"(src))
#define CP_COMMIT() asm volatile("cp.async.commit_group;" ::: "memory")
#define CP_WAIT(n)  asm volatile("cp.async.wait_group %0;" :: "n"(n) : "memory")

#define LDSM4(r, addr)                                                          \
    asm volatile("ldmatrix.sync.aligned.m8n8.x4.shared.b16 {%0,%1,%2,%3}, [%4];" \
        : "=r"((r)[0]), "=r"((r)[1]), "=r"((r)[2]), "=r"((r)[3]) : "r"(addr))

#define MMA(d, a, b)                                                            \
    asm volatile("mma.sync.aligned.m16n8k16.row.col.f32.f16.f16.f32 "           \
        "{%0,%1,%2,%3}, {%4,%5,%6,%7}, {%8,%9}, {%0,%1,%2,%3};"                 \
        : "+f"((d)[0]), "+f"((d)[1]), "+f"((d)[2]), "+f"((d)[3])                \
        : "r"((a)[0]), "r"((a)[1]), "r"((a)[2]), "r"((a)[3]),                   \
          "r"((b)[0]), "r"((b)[1]))

// ---------------- im2col: fp16 hi only, npx==8 always ----------------------
__global__ __launch_bounds__(256) void a_conv_kernel(Imgs imgs, int blk0) {
    __shared__ float sm[14 * 112];
    __shared__ ushort4 s_idx4[49];    // quad q -> smem offsets of f=4q..4q+3
    int blk = blockIdx.x + blk0;
    int im = 0;
#pragma unroll
    for (int i = 1; i < 6; i++) if (blk >= c_cumblk[i]) im = i;
    int local = blk - c_cumblk[im];
    int h = c_h[im], w = c_w[im], W = c_W[im], H = c_H[im], wc = c_wc[im];
    int ch  = local / (h * wc);
    int rem = local - ch * h * wc;
    int py  = rem / wc;
    int qx  = rem - py * wc;
    int px0 = qx * 8;
    int tid = threadIdx.x;

    const float* src = imgs.p[im] + ((size_t)ch * H + py * 14) * W + px0 * 14;
#pragma unroll
    for (int i = 0; i < 7; i++) {           // 14*112 = 1568
        int t = tid + i * 256;
        if (i == 6 && t >= 1568) break;
        int r = t / 112, c = t - r * 112;
        sm[t] = src[(size_t)r * W + c];
    }
    if (tid < 49) {
        int f = tid * 4;
        ushort4 v;
        v.x = (ushort)(((f    ) / 14) * 112 + ((f    ) % 14));
        v.y = (ushort)(((f + 1) / 14) * 112 + ((f + 1) % 14));
        v.z = (ushort)(((f + 2) / 14) * 112 + ((f + 2) % 14));
        v.w = (ushort)(((f + 3) / 14) * 112 + ((f + 3) % 14));
        s_idx4[tid] = v;
    }
    __syncthreads();

    int gpbase = c_off[im] + py * w + px0;
    int chbase = ch * 196;
#pragma unroll
    for (int i = 0; i < 2; i++) {           // 8*49 = 392 quads
        int t = tid + i * 256;
        if (i == 1 && t >= 392) break;
        int px = t / 49;
        int q  = t - px * 49;
        int f  = q * 4;
        int sb = px * 14;
        ushort4 ix = s_idx4[q];
        __half2 h01 = __floats2half2_rn(sm[ix.x + sb], sm[ix.y + sb]);
        __half2 h23 = __floats2half2_rn(sm[ix.z + sb], sm[ix.w + sb]);
        size_t dsth = (size_t)(gpbase + px) * KP + chbase + f;
        *(uint2*)&g_a_hi[dsth] = make_uint2(*(uint32_t*)&h01, *(uint32_t*)&h23);
    }

    if (ch == 2 && tid < 40) {
        int px = tid / 5;
        int j  = tid - px * 5;
        size_t dsth = (size_t)(gpbase + px) * KP + KDIM + j * 4;
        *(uint2*)&g_a_hi[dsth] = make_uint2(0u, 0u);
    }
}

// ---------------- conv_w -> fp16 [N=1280][K=608] ---------------------------
__global__ __launch_bounds__(256) void b_conv_kernel(const float* __restrict__ conv_w) {
    int idx = blockIdx.x * 256 + threadIdx.x;
    if (idx >= E * KP) return;
    int n = idx / KP;
    int k = idx - n * KP;
    float v = (k < KDIM) ? conv_w[n * KDIM + k] : 0.f;
    g_b_hi[idx] = __float2half(v);
}

// ---------------- single-product fp16 HMMA GEMM, tile 64x128, occ 4 --------
// 128 threads = 4 warps (2x2), warp tile 32x64. BK=32, double-buffered.
#define KROW 40
#define A_TILE (64 * KROW * 2)        // 5120
#define B_TILE (128 * KROW * 2)       // 10240
#define STAGE_B (A_TILE + B_TILE)     // 15360
#define SMEM_TOTAL (2 * STAGE_B)      // 30720
#define NITER 19

__global__ __launch_bounds__(128, 4) void gemm_mma(int bm0) {
    extern __shared__ __align__(128) char smem[];
    uint32_t sbase = smem_u32(smem);
    int tid  = threadIdx.x;
    int lane = tid & 31;
    int wid  = tid >> 5;
    int wm = wid >> 1, wn = wid & 1;
    int bm = blockIdx.y + bm0, bn = blockIdx.x;

    const __half* gAhi = g_a_hi + (size_t)bm * 64 * KP;
    const __half* gBhi = g_b_hi + (size_t)bn * 128 * KP;

    float acc[2][8][4];
#pragma unroll
    for (int i = 0; i < 2; i++)
#pragma unroll
        for (int j = 0; j < 8; j++)
#pragma unroll
            for (int q = 0; q < 4; q++) acc[i][j][q] = 0.f;

    // stage = 768 16B chunks, 6 per thread
    auto load_stage = [&](int buf, int k0) {
        uint32_t st = sbase + buf * STAGE_B;
#pragma unroll
        for (int i = 0; i < 6; i++) {
            int c = tid + i * 128;
            const __half* g;
            uint32_t base;
            int row;
            if (c < 256) { g = gAhi; base = 0;      row = c >> 2; }
            else         { g = gBhi; base = A_TILE; row = (c - 256) >> 2; }
            int cg = c & 3;
            CP16(st + base + row * (KROW * 2) + cg * 16,
                 g + (size_t)row * KP + k0 + cg * 8);
        }
        CP_COMMIT();
    };

    load_stage(0, 0);

    int a_row = wm * 32 + (lane & 15);
    int a_cg  = (lane >> 4);
    int b_row = wn * 64 + (lane & 7) + ((lane >> 4) << 3);
    int b_cg  = (lane >> 3) & 1;

    for (int it = 0; it < NITER; it++) {
        if (it + 1 < NITER) load_stage((it + 1) & 1, (it + 1) * 32);
        if (it + 1 < NITER) { CP_WAIT(1); } else { CP_WAIT(0); }
        __syncthreads();

        uint32_t st  = sbase + (it & 1) * STAGE_B;
        uint32_t aHi = st;
        uint32_t bHi = st + A_TILE;

#pragma unroll
        for (int ks = 0; ks < 2; ks++) {
            uint32_t aoff = a_row * (KROW * 2) + (ks * 16 + a_cg * 8) * 2;
            uint32_t boff = b_row * (KROW * 2) + (ks * 16 + b_cg * 8) * 2;

            uint32_t ar[2][4];
            uint32_t bhi[4][4];   // pair pp covers n-tiles 2pp, 2pp+1

#pragma unroll
            for (int pp = 0; pp < 4; pp++)
                LDSM4(bhi[pp], bHi + boff + pp * 16 * (KROW * 2));
#pragma unroll
            for (int mt = 0; mt < 2; mt++)
                LDSM4(ar[mt], aHi + aoff + mt * 16 * (KROW * 2));

#pragma unroll
            for (int mt = 0; mt < 2; mt++)
#pragma unroll
                for (int pp = 0; pp < 4; pp++) {
                    MMA(acc[mt][pp * 2],     ar[mt], (&bhi[pp][0]));
                    MMA(acc[mt][pp * 2 + 1], ar[mt], (&bhi[pp][2]));
                }
        }
        __syncthreads();
    }

    int g = lane >> 2, t = lane & 3;
    int row0 = bm * 64 + wm * 32;
    int col0 = bn * 128 + wn * 64;
#pragma unroll
    for (int mt = 0; mt < 2; mt++) {
#pragma unroll
        for (int nt = 0; nt < 8; nt++) {
            float* p = g_x + (size_t)(row0 + mt * 16 + g) * E + col0 + nt * 8 + t * 2;
            *(float2*)p           = make_float2(acc[mt][nt][0], acc[mt][nt][1]);
            *(float2*)(p + 8 * E) = make_float2(acc[mt][nt][2], acc[mt][nt][3]);
        }
    }
}

// ---------------- pos-embed interp + bias + LayerNorm + scatter ------------
__global__ __launch_bounds__(256) void ln_kernel(const float* __restrict__ conv_b,
                                                 const float* __restrict__ pos_table,
                                                 const float* __restrict__ ln_w,
                                                 const float* __restrict__ ln_b,
                                                 float* __restrict__ out, int goff) {
    int gp = blockIdx.x + goff;
    int im = 0;
#pragma unroll
    for (int i = 1; i < 6; i++) if (gp >= c_off[i]) im = i;
    int p = gp - c_off[im];
    int h = c_h[im], w = c_w[im];
    int py = p / w, px = p - py * w;

    float cy = (py + 0.5f) * (32.0f / (float)h) - 0.5f;
    cy = fminf(fmaxf(cy, 0.f), 31.f);
    float cx = (px + 0.5f) * (32.0f / (float)w) - 0.5f;
    cx = fminf(fmaxf(cx, 0.f), 31.f);
    int y0 = (int)cy; int y1 = min(y0 + 1, 31); float fy = cy - (float)y0;
    int x0 = (int)cx; int x1 = min(x0 + 1, 31); float fx = cx - (float)x0;

    const float* T00 = pos_table + (size_t)(1 + y0 * 32 + x0) * E;
    const float* T01 = pos_table + (size_t)(1 + y0 * 32 + x1) * E;
    const float* T10 = pos_table + (size_t)(1 + y1 * 32 + x0) * E;
    const float* T11 = pos_table + (size_t)(1 + y1 * 32 + x1) * E;
    float w00 = (1.f - fy) * (1.f - fx), w01 = (1.f - fy) * fx;
    float w10 = fy * (1.f - fx), w11 = fy * fx;

    int tid = threadIdx.x;
    float y[5];
    float s = 0.f, ss = 0.f;
#pragma unroll
    for (int i = 0; i < 5; i++) {
        int f = tid + i * 256;
        float v = g_x[(size_t)gp * E + f] + conv_b[f]
                + w00 * T00[f] + w01 * T01[f] + w10 * T10[f] + w11 * T11[f];
        y[i] = v;
        s += v;
        ss += v * v;
    }

    __shared__ float rs[8], rss[8];
#pragma unroll
    for (int o = 16; o > 0; o >>= 1) {
        s  += __shfl_xor_sync(0xffffffffu, s, o);
        ss += __shfl_xor_sync(0xffffffffu, ss, o);
    }
    if ((tid & 31) == 0) { rs[tid >> 5] = s; rss[tid >> 5] = ss; }
    __syncthreads();
    __shared__ float fm, finv;
    if (tid == 0) {
        float S = 0.f, SS = 0.f;
#pragma unroll
        for (int i = 0; i < 8; i++) { S += rs[i]; SS += rss[i]; }
        float m = S / (float)E;
        fm = m;
        finv = rsqrtf(SS / (float)E - m * m + 1e-5f);
    }
    __syncthreads();
    float m = fm, inv = finv;

    int row = c_bi[im] * MAXSEQ + c_s[im] + p;
    float* o = out + (size_t)row * E;
#pragma unroll
    for (int i = 0; i < 5; i++) {
        int f = tid + i * 256;
        o[f] = (y[i] - m) * inv * ln_w[f] + ln_b[f];
    }
}

// ---------------- merged fill: mask (blocks 0..2559) + zero (2560..5119) ---
__global__ __launch_bounds__(256) void fill_kernel(float4* __restrict__ out,
                                                   float4* __restrict__ mask) {
    int blk = blockIdx.x;
    int tid = threadIdx.x;
    if (blk < 2560) {
        int b  = blk >> 9;
        int r0 = (blk & 511) * 4;
        const int* iv = c_iv[b];
        int lo = -1, hi = -1;
        if (r0 >= iv[0] && r0 < iv[1]) { lo = iv[0]; hi = iv[1]; }
        else if (iv[3] > iv[2] && r0 >= iv[2] && r0 < iv[3]) { lo = iv[2]; hi = iv[3]; }
        float4* base = mask + ((size_t)(b * MAXSEQ + r0) * MAXSEQ) / 4;
#pragma unroll
        for (int i = 0; i < 8; i++) {
            int fidx = tid + i * 256;
            int col  = (fidx & 511) * 4;
            float v = (col >= lo && col < hi) ? 1.f : 0.f;
            base[fidx] = make_float4(v, v, v, v);
        }
    } else {
        int zb = blk - 2560;
        int b  = zb >> 9;
        int r0 = (zb & 511) * 4;
        if (r0 + 4 <= c_cov[b]) return;
        float4* base = out + ((size_t)(b * MAXSEQ + r0) * E) / 4;
        float4 z = make_float4(0.f, 0.f, 0.f, 0.f);
#pragma unroll
        for (int i = 0; i < 5; i++) base[tid + i * 256] = z;
    }
}

// ---------------- launch: 3-stream pipelined schedule (R16) -----------------
extern "C" void kernel_launch(void* const* d_in, const int* in_sizes, int n_in,
                              void* d_out, int out_size) {
    Imgs imgs;
    for (int i = 0; i < 6; i++) imgs.p[i] = (const float*)d_in[i];
    const float* conv_w = (const float*)d_in[6];
    const float* conv_b = (const float*)d_in[7];
    const float* pos    = (const float*)d_in[8];
    const float* ln_w   = (const float*)d_in[9];
    const float* ln_b   = (const float*)d_in[10];

    float* out  = (float*)d_out;
    float* mask = out + (size_t)NB * MAXSEQ * E;

    static cudaStream_t s2 = nullptr, s3 = nullptr;
    static cudaEvent_t ev_fork = nullptr, ev_b = nullptr, ev_aB = nullptr,
                       ev_fill = nullptr, ev_g1a = nullptr, ev_g1b = nullptr,
                       ev_ln1 = nullptr;
    if (!s2) {
        cudaStreamCreateWithFlags(&s2, cudaStreamNonBlocking);
        cudaStreamCreateWithFlags(&s3, cudaStreamNonBlocking);
        cudaEventCreateWithFlags(&ev_fork, cudaEventDisableTiming);
        cudaEventCreateWithFlags(&ev_b, cudaEventDisableTiming);
        cudaEventCreateWithFlags(&ev_aB, cudaEventDisableTiming);
        cudaEventCreateWithFlags(&ev_fill, cudaEventDisableTiming);
        cudaEventCreateWithFlags(&ev_g1a, cudaEventDisableTiming);
        cudaEventCreateWithFlags(&ev_g1b, cudaEventDisableTiming);
        cudaEventCreateWithFlags(&ev_ln1, cudaEventDisableTiming);
        cudaFuncSetAttribute(gemm_mma, cudaFuncAttributeMaxDynamicSharedMemorySize,
                             SMEM_TOTAL);
    }

    // fork
    cudaEventRecord(ev_fork, 0);
    cudaStreamWaitEvent(s2, ev_fork, 0);
    cudaStreamWaitEvent(s3, ev_fork, 0);

    // s2: b_conv -> a_convB (images 3-5) -> fill; later ln1
    b_conv_kernel<<<(E * KP + 255) / 256, 256, 0, s2>>>(conv_w);
    cudaEventRecord(ev_b, s2);
    a_conv_kernel<<<2256 - 1176, 256, 0, s2>>>(imgs, 1176);
    cudaEventRecord(ev_aB, s2);
    fill_kernel<<<5120, 256, 0, s2>>>((float4*)out, (float4*)mask);
    cudaEventRecord(ev_fill, s2);

    // s3: a_conv images 1-2 (blocks 384..1175) -> gemm1b (bm 16..48)
    a_conv_kernel<<<1176 - 384, 256, 0, s3>>>(imgs, 384);
    cudaStreamWaitEvent(s3, ev_b, 0);
    gemm_mma<<<dim3(E / 128, 33), 128, SMEM_TOTAL, s3>>>(16);
    cudaEventRecord(ev_g1b, s3);

    // s0: a_conv image 0 (blocks 0..383) -> gemm1a (bm 0..15)
    a_conv_kernel<<<384, 256>>>(imgs, 0);
    cudaStreamWaitEvent(0, ev_b, 0);
    gemm_mma<<<dim3(E / 128, 16), 128, SMEM_TOTAL>>>(0);
    cudaEventRecord(ev_g1a, 0);

    // s2: ln1 (rows 0..3135) after gemm1a + gemm1b, overlaps gemm2
    cudaStreamWaitEvent(s2, ev_g1a, 0);
    cudaStreamWaitEvent(s2, ev_g1b, 0);
    ln_kernel<<<3136, 256, 0, s2>>>(conv_b, pos, ln_w, ln_b, out, 0);
    cudaEventRecord(ev_ln1, s2);

    // s0: gemm2 (bm 49..93, rows 3136..6015 — needs a_convB) -> ln2
    cudaStreamWaitEvent(0, ev_aB, 0);
    gemm_mma<<<dim3(E / 128, 45), 128, SMEM_TOTAL>>>(49);
    ln_kernel<<<NPATCH - 3136, 256>>>(conv_b, pos, ln_w, ln_b, out, 3136);

    // join
    cudaStreamWaitEvent(0, ev_ln1, 0);
    cudaStreamWaitEvent(0, ev_fill, 0);
}